// round 14
// baseline (speedup 1.0000x reference)
#include <cuda_runtime.h>
#include <math.h>
#include <stdint.h>

// Problem constants
#define BB   2
#define SS   2048
#define LL   1024
#define HH   16
#define HKK  4
#define DD   64
#define MROWS (BB*SS)            // 4096
#define QKVN  ((HH + 2*HKK)*DD)  // 1536 (only the used columns of w_qkv)

// Scratch (allocation-free rule: __device__ globals). All tf32-in-u32.
__device__ unsigned g_x32 [MROWS * LL];     // x converted to tf32
__device__ unsigned g_w1  [QKVN * LL];      // w_qkv[0:1536] converted
__device__ unsigned g_w2  [LL * LL];        // w_out converted
__device__ unsigned g_qkv [MROWS * QKVN];   // qkv proj (Q cols pre-scaled), tf32
__device__ unsigned g_attn[MROWS * LL];     // attention output, tf32

// ---------------------------------------------------------------------------
// TF32 / cp.async helpers
// ---------------------------------------------------------------------------
__device__ __forceinline__ unsigned f2tf(float f) {
    unsigned u;
    asm("cvt.rna.tf32.f32 %0, %1;" : "=r"(u) : "f"(f));
    return u;
}

__device__ __forceinline__ void mma8(float* c, const unsigned* a, const unsigned* b) {
    asm volatile(
        "mma.sync.aligned.m16n8k8.row.col.f32.tf32.tf32.f32 "
        "{%0,%1,%2,%3}, {%4,%5,%6,%7}, {%8,%9}, {%0,%1,%2,%3};"
        : "+f"(c[0]), "+f"(c[1]), "+f"(c[2]), "+f"(c[3])
        : "r"(a[0]), "r"(a[1]), "r"(a[2]), "r"(a[3]),
          "r"(b[0]), "r"(b[1]));
}

__device__ __forceinline__ uint32_t smem_u32(const void* p) {
    uint32_t a;
    asm("{ .reg .u64 t; cvta.to.shared.u64 t, %1; cvt.u32.u64 %0, t; }"
        : "=r"(a) : "l"(p));
    return a;
}

__device__ __forceinline__ void cp16(uint32_t dst, const void* src) {
    asm volatile("cp.async.cg.shared.global [%0], [%1], 16;"
                 :: "r"(dst), "l"(src));
}
#define CP_COMMIT() asm volatile("cp.async.commit_group;" ::: "memory")
#define CP_WAIT0()  asm volatile("cp.async.wait_group 0;"  ::: "memory")
#define CP_WAIT1()  asm volatile("cp.async.wait_group 1;"  ::: "memory")

// ---------------------------------------------------------------------------
// One-time fp32 -> tf32 conversion
// ---------------------------------------------------------------------------
__global__ __launch_bounds__(256)
void cvt_kernel(const float* __restrict__ src, unsigned* __restrict__ dst)
{
    const int i = (blockIdx.x * 256 + threadIdx.x) * 4;
    float4 v = *(const float4*)(src + i);
    *(uint4*)(dst + i) = make_uint4(f2tf(v.x), f2tf(v.y), f2tf(v.z), f2tf(v.w));
}

// ---------------------------------------------------------------------------
// QKV GEMM: 64x128 tiles, 128 threads (4 warps, each 64x32), 4 CTAs/SM.
// Same per-warp fragment pattern as the proven 128x128 kernel (wm = 0), but
// 768 CTAs over 592 resident slots -> near-full tail wave (was 384/296 = 2
// full waves with a 30%-occupied second wave).
// C written as tf32 u32; Q columns (bn < 1024) pre-scaled by 0.125.
// ---------------------------------------------------------------------------
#define BKS 20

__global__ __launch_bounds__(128, 4)
void qkv_gemm_kernel()
{
    __shared__ unsigned As[2][64 * BKS];     // 10 KB
    __shared__ unsigned Bs[2][128 * BKS];    // 20 KB

    const unsigned* A = g_x32;
    const unsigned* B = g_w1;
    const int K = LL;

    const int bm   = blockIdx.y << 6;
    const int bn   = blockIdx.x << 7;
    const int tid  = threadIdx.x;
    const int lane = tid & 31;
    const int wn   = tid >> 5;       // 0..3
    const int g    = lane >> 2;
    const int t4   = lane & 3;

    // staging map: chunk id -> row id>>2, col (id&3)*4 ; ids tid + 128*j
    const int sr = tid >> 2;             // 0..31
    const int sc = (tid & 3) << 2;       // 0,4,8,12
    const unsigned* Ag0 = A + (size_t)(bm + sr)      * K + sc;
    const unsigned* Ag1 = A + (size_t)(bm + sr + 32) * K + sc;
    const unsigned* Bg0 = B + (size_t)(bn + sr)      * K + sc;
    const unsigned* Bg1 = B + (size_t)(bn + sr + 32) * K + sc;
    const unsigned* Bg2 = B + (size_t)(bn + sr + 64) * K + sc;
    const unsigned* Bg3 = B + (size_t)(bn + sr + 96) * K + sc;

    const uint32_t asb = smem_u32(As) + (sr * BKS + sc) * 4;
    const uint32_t bsb = smem_u32(Bs) + (sr * BKS + sc) * 4;
    const uint32_t r32  = 32 * BKS * 4;
    const uint32_t bufA = 64 * BKS * 4;
    const uint32_t bufB = 128 * BKS * 4;

    float acc[4][4][4];
#pragma unroll
    for (int mt = 0; mt < 4; mt++)
#pragma unroll
        for (int nt = 0; nt < 4; nt++)
#pragma unroll
            for (int r = 0; r < 4; r++) acc[mt][nt][r] = 0.f;

    const int NT = K >> 4;   // 64

    // stage tile 0
    cp16(asb,           Ag0);
    cp16(asb + r32,     Ag1);
    cp16(bsb,           Bg0);
    cp16(bsb + r32,     Bg1);
    cp16(bsb + 2 * r32, Bg2);
    cp16(bsb + 3 * r32, Bg3);
    CP_COMMIT();
    CP_WAIT0();
    __syncthreads();

    for (int kt = 0; kt < NT; kt++) {
        const int cur = kt & 1;
        if (kt + 1 < NT) {
            const int ko = (kt + 1) << 4;
            const uint32_t oa = ((kt + 1) & 1) * bufA;
            const uint32_t ob = ((kt + 1) & 1) * bufB;
            cp16(asb + oa,           Ag0 + ko);
            cp16(asb + oa + r32,     Ag1 + ko);
            cp16(bsb + ob,           Bg0 + ko);
            cp16(bsb + ob + r32,     Bg1 + ko);
            cp16(bsb + ob + 2 * r32, Bg2 + ko);
            cp16(bsb + ob + 3 * r32, Bg3 + ko);
            CP_COMMIT();
        }
        const unsigned* as = As[cur];
        const unsigned* bs = Bs[cur];

#pragma unroll
        for (int ks = 0; ks < 2; ks++) {
            const int kb = ks * 8;
            unsigned af[4][4], bf[4][2];
#pragma unroll
            for (int mt = 0; mt < 4; mt++) {
                const int row = mt * 16 + g;
                af[mt][0] = as[ row      * BKS + kb + t4];
                af[mt][1] = as[(row + 8) * BKS + kb + t4];
                af[mt][2] = as[ row      * BKS + kb + t4 + 4];
                af[mt][3] = as[(row + 8) * BKS + kb + t4 + 4];
            }
#pragma unroll
            for (int nt = 0; nt < 4; nt++) {
                const int nr = wn * 32 + nt * 8 + g;
                bf[nt][0] = bs[nr * BKS + kb + t4];
                bf[nt][1] = bs[nr * BKS + kb + t4 + 4];
            }
#pragma unroll
            for (int mt = 0; mt < 4; mt++)
#pragma unroll
                for (int nt = 0; nt < 4; nt++)
                    mma8(acc[mt][nt], af[mt], bf[nt]);
        }

        if (kt + 1 < NT) {
            CP_WAIT0();
            __syncthreads();
        }
    }

    // epilogue: tf32 out, Q columns pre-scaled (N boundary 1024 = 8*128)
    const float s = (bn < 1024) ? 0.125f : 1.0f;
#pragma unroll
    for (int mt = 0; mt < 4; mt++) {
        const int row = bm + mt * 16 + g;
#pragma unroll
        for (int nt = 0; nt < 4; nt++) {
            const int col = bn + wn * 32 + nt * 8 + 2 * t4;
            *(uint2*)(g_qkv + (size_t)row * QKVN + col) =
                make_uint2(f2tf(acc[mt][nt][0] * s), f2tf(acc[mt][nt][1] * s));
            *(uint2*)(g_qkv + (size_t)(row + 8) * QKVN + col) =
                make_uint2(f2tf(acc[mt][nt][2] * s), f2tf(acc[mt][nt][3] * s));
        }
    }
}

// ---------------------------------------------------------------------------
// Output GEMM (proven R13 config): 128x128, 256 threads, 2(M)x4(N) warps.
// ---------------------------------------------------------------------------
__global__ __launch_bounds__(256, 2)
void out_gemm_kernel(float* __restrict__ out)
{
    __shared__ unsigned As[2][128 * BKS];
    __shared__ unsigned Bs[2][128 * BKS];

    const unsigned* A = g_attn;
    const unsigned* B = g_w2;
    const int K = LL, N = LL;

    const int bm   = blockIdx.y << 7;
    const int bn   = blockIdx.x << 7;
    const int tid  = threadIdx.x;
    const int lane = tid & 31;
    const int wid  = tid >> 5;
    const int wm   = wid >> 2;
    const int wn   = wid & 3;
    const int g    = lane >> 2;
    const int t4   = lane & 3;

    const int r0 = tid >> 2;
    const int c0 = (tid & 3) << 2;
    const unsigned* Ag0 = A + (size_t)(bm + r0)      * K + c0;
    const unsigned* Ag1 = A + (size_t)(bm + r0 + 64) * K + c0;
    const unsigned* Bg0 = B + (size_t)(bn + r0)      * K + c0;
    const unsigned* Bg1 = B + (size_t)(bn + r0 + 64) * K + c0;

    const uint32_t asb = smem_u32(As) + (r0 * BKS + c0) * 4;
    const uint32_t bsb = smem_u32(Bs) + (r0 * BKS + c0) * 4;
    const uint32_t bufB = 128 * BKS * 4;
    const uint32_t row64 = 64 * BKS * 4;

    float acc[4][4][4];
#pragma unroll
    for (int mt = 0; mt < 4; mt++)
#pragma unroll
        for (int nt = 0; nt < 4; nt++)
#pragma unroll
            for (int r = 0; r < 4; r++) acc[mt][nt][r] = 0.f;

    const int NT = K >> 4;

    cp16(asb,         Ag0);
    cp16(asb + row64, Ag1);
    cp16(bsb,         Bg0);
    cp16(bsb + row64, Bg1);
    CP_COMMIT();
    CP_WAIT0();
    __syncthreads();

    for (int kt = 0; kt < NT; kt++) {
        const int cur = kt & 1;
        if (kt + 1 < NT) {
            const int ko = (kt + 1) << 4;
            const uint32_t off = ((kt + 1) & 1) * bufB;
            cp16(asb + off,         Ag0 + ko);
            cp16(asb + off + row64, Ag1 + ko);
            cp16(bsb + off,         Bg0 + ko);
            cp16(bsb + off + row64, Bg1 + ko);
            CP_COMMIT();
        }
        const unsigned* as = As[cur];
        const unsigned* bs = Bs[cur];

#pragma unroll
        for (int ks = 0; ks < 2; ks++) {
            const int kb = ks * 8;
            unsigned af[4][4], bf[4][2];
#pragma unroll
            for (int mt = 0; mt < 4; mt++) {
                const int row = wm * 64 + mt * 16 + g;
                af[mt][0] = as[ row      * BKS + kb + t4];
                af[mt][1] = as[(row + 8) * BKS + kb + t4];
                af[mt][2] = as[ row      * BKS + kb + t4 + 4];
                af[mt][3] = as[(row + 8) * BKS + kb + t4 + 4];
            }
#pragma unroll
            for (int nt = 0; nt < 4; nt++) {
                const int nr = wn * 32 + nt * 8 + g;
                bf[nt][0] = bs[nr * BKS + kb + t4];
                bf[nt][1] = bs[nr * BKS + kb + t4 + 4];
            }
#pragma unroll
            for (int mt = 0; mt < 4; mt++)
#pragma unroll
                for (int nt = 0; nt < 4; nt++)
                    mma8(acc[mt][nt], af[mt], bf[nt]);
        }

        if (kt + 1 < NT) {
            CP_WAIT0();
            __syncthreads();
        }
    }

#pragma unroll
    for (int mt = 0; mt < 4; mt++) {
        const int row = bm + wm * 64 + mt * 16 + g;
#pragma unroll
        for (int nt = 0; nt < 4; nt++) {
            const int col = bn + wn * 32 + nt * 8 + 2 * t4;
            *(float2*)(out + (size_t)row * N + col) =
                make_float2(acc[mt][nt][0], acc[mt][nt][1]);
            *(float2*)(out + (size_t)(row + 8) * N + col) =
                make_float2(acc[mt][nt][2], acc[mt][nt][3]);
        }
    }
}

// ---------------------------------------------------------------------------
// Flash attention, causal, TF32 tensor cores.
// R13 structure + DOUBLE-BUFFERED K/V via cp.async prefetch (wait_group 1):
// memory latency of the next KV block hides behind QK/softmax/PV of the
// current one. Smem 104KB -> still 2 CTAs/SM.
// ---------------------------------------------------------------------------
#define QTILE 128
#define AST 68
#define VST 72
#define KVSZ (64 * AST + 64 * VST)                 // 8960 u32 per stage
#define ATTN_SMEM ((QTILE * AST + 2 * KVSZ) * 4)   // 106496 B

__global__ __launch_bounds__(256, 2)
void attn_kernel()
{
    extern __shared__ unsigned sm[];
    unsigned* Qs = sm;                                // [128][68], tf32 (pre-scaled)

    const int qb   = gridDim.x - 1 - blockIdx.x;      // heavy first
    const int h    = blockIdx.y;
    const int b    = blockIdx.z;
    const int hk   = h >> 2;
    const int tid  = threadIdx.x;
    const int lane = tid & 31;
    const int w    = tid >> 5;
    const int g    = lane >> 2;
    const int t4   = lane & 3;
    const int R0   = 16 * w + g;
    const int gR0  = qb * QTILE + R0;

    const uint32_t qs_b  = smem_u32(Qs);
    const uint32_t kv0_b = qs_b + QTILE * AST * 4;

    auto stage_kv = [&](int buf, int kb) {
        const unsigned* kbase = g_qkv + (size_t)(b * SS + kb * 64) * QKVN
                                + HH * DD + hk * DD;
        const uint32_t ks_b = kv0_b + buf * (KVSZ * 4);
        const uint32_t vs_b = ks_b + 64 * AST * 4;
#pragma unroll
        for (int i = 0; i < 4; i++) {
            const int e = tid + i * 256;
            const int r = e >> 4, c = (e & 15) << 2;
            const unsigned* p = kbase + (size_t)r * QKVN + c;
            cp16(ks_b + (r * AST + c) * 4, p);
            cp16(vs_b + (r * VST + c) * 4, p + HKK * DD);
        }
    };

    // ---- group 0: Q tile + KV block 0 ----
    {
        const unsigned* qbase = g_qkv + (size_t)(b * SS + qb * QTILE) * QKVN + h * DD;
#pragma unroll
        for (int i = 0; i < 8; i++) {
            const int e = tid + i * 256;
            const int r = e >> 4, c = (e & 15) << 2;
            cp16(qs_b + (r * AST + c) * 4, qbase + (size_t)r * QKVN + c);
        }
        stage_kv(0, 0);
        CP_COMMIT();
    }

    float m0 = -1e30f, m1 = -1e30f, l0 = 0.f, l1 = 0.f;
    float oacc[8][4];
#pragma unroll
    for (int nt = 0; nt < 8; nt++)
#pragma unroll
        for (int r = 0; r < 4; r++) oacc[nt][r] = 0.f;

    const int kb_max = 2 * qb + 1;
    for (int kb = 0; kb <= kb_max; kb++) {
        // prefetch next KV block, then wait for current
        if (kb < kb_max) {
            stage_kv((kb + 1) & 1, kb + 1);
            CP_COMMIT();
            CP_WAIT1();
        } else {
            CP_WAIT0();
        }
        __syncthreads();

        const unsigned* Ks = sm + QTILE * AST + (kb & 1) * KVSZ;
        const unsigned* Vs = Ks + 64 * AST;

        const bool active = (kb * 64 <= qb * QTILE + 16 * w + 15);
        if (active) {
            // ---- S = Q K^T (m16 x n64 per warp) ----
            float sacc[8][4];
#pragma unroll
            for (int nt = 0; nt < 8; nt++)
#pragma unroll
                for (int r = 0; r < 4; r++) sacc[nt][r] = 0.f;

#pragma unroll
            for (int kk = 0; kk < 8; kk++) {
                const int kp = kk * 8;
                unsigned af[4];
                af[0] = Qs[ R0      * AST + kp + t4];
                af[1] = Qs[(R0 + 8) * AST + kp + t4];
                af[2] = Qs[ R0      * AST + kp + t4 + 4];
                af[3] = Qs[(R0 + 8) * AST + kp + t4 + 4];
#pragma unroll
                for (int nt = 0; nt < 8; nt++) {
                    unsigned bf[2];
                    bf[0] = Ks[(nt * 8 + g) * AST + kp + t4];
                    bf[1] = Ks[(nt * 8 + g) * AST + kp + t4 + 4];
                    mma8(sacc[nt], af, bf);
                }
            }

            // ---- causal mask ----
            if (kb * 64 + 63 > qb * QTILE + 16 * w) {
#pragma unroll
                for (int nt = 0; nt < 8; nt++) {
                    const int cc = kb * 64 + nt * 8 + 2 * t4;
                    if (cc     > gR0)     sacc[nt][0] = -1e30f;
                    if (cc + 1 > gR0)     sacc[nt][1] = -1e30f;
                    if (cc     > gR0 + 8) sacc[nt][2] = -1e30f;
                    if (cc + 1 > gR0 + 8) sacc[nt][3] = -1e30f;
                }
            }

            // ---- online softmax ----
            float mx0 = -1e30f, mx1 = -1e30f;
#pragma unroll
            for (int nt = 0; nt < 8; nt++) {
                mx0 = fmaxf(mx0, fmaxf(sacc[nt][0], sacc[nt][1]));
                mx1 = fmaxf(mx1, fmaxf(sacc[nt][2], sacc[nt][3]));
            }
            mx0 = fmaxf(mx0, __shfl_xor_sync(0xffffffffu, mx0, 1));
            mx0 = fmaxf(mx0, __shfl_xor_sync(0xffffffffu, mx0, 2));
            mx1 = fmaxf(mx1, __shfl_xor_sync(0xffffffffu, mx1, 1));
            mx1 = fmaxf(mx1, __shfl_xor_sync(0xffffffffu, mx1, 2));

            const float mn0 = fmaxf(m0, mx0);
            const float mn1 = fmaxf(m1, mx1);
            float sum0 = 0.f, sum1 = 0.f;
#pragma unroll
            for (int nt = 0; nt < 8; nt++) {
                sacc[nt][0] = __expf(sacc[nt][0] - mn0);
                sacc[nt][1] = __expf(sacc[nt][1] - mn0);
                sacc[nt][2] = __expf(sacc[nt][2] - mn1);
                sacc[nt][3] = __expf(sacc[nt][3] - mn1);
                sum0 += sacc[nt][0] + sacc[nt][1];
                sum1 += sacc[nt][2] + sacc[nt][3];
            }
            sum0 += __shfl_xor_sync(0xffffffffu, sum0, 1);
            sum0 += __shfl_xor_sync(0xffffffffu, sum0, 2);
            sum1 += __shfl_xor_sync(0xffffffffu, sum1, 1);
            sum1 += __shfl_xor_sync(0xffffffffu, sum1, 2);

            const float a0 = __expf(m0 - mn0);
            const float a1 = __expf(m1 - mn1);
            l0 = l0 * a0 + sum0;  m0 = mn0;
            l1 = l1 * a1 + sum1;  m1 = mn1;
#pragma unroll
            for (int nt = 0; nt < 8; nt++) {
                oacc[nt][0] *= a0; oacc[nt][1] *= a0;
                oacc[nt][2] *= a1; oacc[nt][3] *= a1;
            }

            // ---- O += P*V (register repack via quad shuffles) ----
            const int sA = (lane & ~3) | (t4 >> 1);
            const int sB = sA + 2;
            const bool odd = (t4 & 1);
#pragma unroll
            for (int kk = 0; kk < 8; kk++) {
                float v0A = __shfl_sync(0xffffffffu, sacc[kk][0], sA);
                float v1A = __shfl_sync(0xffffffffu, sacc[kk][1], sA);
                float v2A = __shfl_sync(0xffffffffu, sacc[kk][2], sA);
                float v3A = __shfl_sync(0xffffffffu, sacc[kk][3], sA);
                float v0B = __shfl_sync(0xffffffffu, sacc[kk][0], sB);
                float v1B = __shfl_sync(0xffffffffu, sacc[kk][1], sB);
                float v2B = __shfl_sync(0xffffffffu, sacc[kk][2], sB);
                float v3B = __shfl_sync(0xffffffffu, sacc[kk][3], sB);
                unsigned af[4];
                af[0] = f2tf(odd ? v1A : v0A);
                af[1] = f2tf(odd ? v3A : v2A);
                af[2] = f2tf(odd ? v1B : v0B);
                af[3] = f2tf(odd ? v3B : v2B);
                const int kp = kk * 8;
#pragma unroll
                for (int nt = 0; nt < 8; nt++) {
                    unsigned bf[2];
                    bf[0] = Vs[(kp + t4)     * VST + nt * 8 + g];
                    bf[1] = Vs[(kp + t4 + 4) * VST + nt * 8 + g];
                    mma8(oacc[nt], af, bf);
                }
            }
        }
        __syncthreads();   // protect buffer (kb&1) before restage at kb+2
    }

    // ---- normalize + store tf32 (head-major [b,s,h,d]) ----
    const float inv0 = 1.f / l0;
    const float inv1 = 1.f / l1;
    unsigned* ob = g_attn + (size_t)(b * SS + qb * QTILE) * LL + h * DD;
#pragma unroll
    for (int nt = 0; nt < 8; nt++) {
        const int cc = nt * 8 + 2 * t4;
        *(uint2*)(ob + (size_t)R0 * LL + cc) =
            make_uint2(f2tf(oacc[nt][0] * inv0), f2tf(oacc[nt][1] * inv0));
        *(uint2*)(ob + (size_t)(R0 + 8) * LL + cc) =
            make_uint2(f2tf(oacc[nt][2] * inv1), f2tf(oacc[nt][3] * inv1));
    }
}

// ---------------------------------------------------------------------------
extern "C" void kernel_launch(void* const* d_in, const int* in_sizes, int n_in,
                              void* d_out, int out_size)
{
    const float* x = nullptr;
    const float* w_qkv = nullptr;
    const float* w_out = nullptr;
    for (int i = 0; i < n_in; i++) {
        if      (in_sizes[i] == 4194304) x     = (const float*)d_in[i];
        else if (in_sizes[i] == 3670016) w_qkv = (const float*)d_in[i];
        else if (in_sizes[i] == 1048576) w_out = (const float*)d_in[i];
    }
    float* out = (float*)d_out;

    static bool attr_set = false;
    if (!attr_set) {
        cudaFuncSetAttribute(attn_kernel,
                             cudaFuncAttributeMaxDynamicSharedMemorySize,
                             ATTN_SMEM);
        attr_set = true;
    }

    unsigned* d_x32; cudaGetSymbolAddress((void**)&d_x32, g_x32);
    unsigned* d_w1;  cudaGetSymbolAddress((void**)&d_w1,  g_w1);
    unsigned* d_w2;  cudaGetSymbolAddress((void**)&d_w2,  g_w2);

    // 0) one-time tf32 conversion of inputs
    cvt_kernel<<<(MROWS * LL) / 1024, 256>>>(x, d_x32);
    cvt_kernel<<<(QKVN  * LL) / 1024, 256>>>(w_qkv, d_w1);
    cvt_kernel<<<(LL    * LL) / 1024, 256>>>(w_out, d_w2);

    // 1) fused QKV projection -> g_qkv (tf32, Q pre-scaled): 64x128 tiles
    qkv_gemm_kernel<<<dim3(QKVN / 128, MROWS / 64), 128>>>();

    // 2) causal GQA flash attention -> g_attn (tf32), double-buffered KV
    attn_kernel<<<dim3(SS / QTILE, HH, BB), 256, ATTN_SMEM>>>();

    // 3) output projection -> out (fp32)
    out_gemm_kernel<<<dim3(LL / 128, MROWS / 128), 256>>>(out);
}

// round 15
// speedup vs baseline: 1.0108x; 1.0108x over previous
#include <cuda_runtime.h>
#include <math.h>
#include <stdint.h>

// Problem constants
#define BB   2
#define SS   2048
#define LL   1024
#define HH   16
#define HKK  4
#define DD   64
#define MROWS (BB*SS)            // 4096
#define QKVN  ((HH + 2*HKK)*DD)  // 1536 (only the used columns of w_qkv)

// Scratch (allocation-free rule: __device__ globals). All tf32-in-u32.
__device__ unsigned g_x32 [MROWS * LL];     // x converted to tf32
__device__ unsigned g_w1  [QKVN * LL];      // w_qkv[0:1536] converted
__device__ unsigned g_w2  [LL * LL];        // w_out converted
__device__ unsigned g_qkv [MROWS * QKVN];   // qkv proj (Q cols pre-scaled), tf32
__device__ unsigned g_attn[MROWS * LL];     // attention output, tf32

// ---------------------------------------------------------------------------
// TF32 / cp.async helpers
// ---------------------------------------------------------------------------
__device__ __forceinline__ unsigned f2tf(float f) {
    unsigned u;
    asm("cvt.rna.tf32.f32 %0, %1;" : "=r"(u) : "f"(f));
    return u;
}

__device__ __forceinline__ void mma8(float* c, const unsigned* a, const unsigned* b) {
    asm volatile(
        "mma.sync.aligned.m16n8k8.row.col.f32.tf32.tf32.f32 "
        "{%0,%1,%2,%3}, {%4,%5,%6,%7}, {%8,%9}, {%0,%1,%2,%3};"
        : "+f"(c[0]), "+f"(c[1]), "+f"(c[2]), "+f"(c[3])
        : "r"(a[0]), "r"(a[1]), "r"(a[2]), "r"(a[3]),
          "r"(b[0]), "r"(b[1]));
}

__device__ __forceinline__ uint32_t smem_u32(const void* p) {
    uint32_t a;
    asm("{ .reg .u64 t; cvta.to.shared.u64 t, %1; cvt.u32.u64 %0, t; }"
        : "=r"(a) : "l"(p));
    return a;
}

__device__ __forceinline__ void cp16(uint32_t dst, const void* src) {
    asm volatile("cp.async.cg.shared.global [%0], [%1], 16;"
                 :: "r"(dst), "l"(src));
}
#define CP_COMMIT() asm volatile("cp.async.commit_group;" ::: "memory")
#define CP_WAIT0()  asm volatile("cp.async.wait_group 0;"  ::: "memory")
#define CP_WAIT1()  asm volatile("cp.async.wait_group 1;"  ::: "memory")
#define CP_WAIT2()  asm volatile("cp.async.wait_group 2;"  ::: "memory")

// ---------------------------------------------------------------------------
// One-time fp32 -> tf32 conversion
// ---------------------------------------------------------------------------
__global__ __launch_bounds__(256)
void cvt_kernel(const float* __restrict__ src, unsigned* __restrict__ dst)
{
    const int i = (blockIdx.x * 256 + threadIdx.x) * 4;
    float4 v = *(const float4*)(src + i);
    *(uint4*)(dst + i) = make_uint4(f2tf(v.x), f2tf(v.y), f2tf(v.z), f2tf(v.w));
}

// ---------------------------------------------------------------------------
// TF32 tensor-core GEMM (NT), 4-STAGE cp.async pipeline.
// 128x128 CTA tile, BK=16, 256 threads, warps 2(M)x4(N) -> 64x32 warp tiles
// (proven fragment pattern). Stride-20 rows: conflict-free fragment LDS.
// Pipeline: prologue stages tiles 0..2; per iter: wait_group 2 (tile kt
// landed), sync, prefetch tile kt+3 into buf (kt+3)&3 == (kt-1)&3 (free
// after the sync), unconditional commit (exact group accounting in tail),
// compute tile kt. ~3 compute-slabs of latency cover vs depth-2's ~0.
// ---------------------------------------------------------------------------
#define BKS 20
#define STG 4
#define TILE_U (128 * BKS)                      // u32 per matrix per stage
#define GEMM_SMEM (STG * 2 * TILE_U * 4)        // 81920 B -> 2 CTAs/SM

template <bool TF32OUT>
__device__ __forceinline__
void gemm4_nt(const unsigned* __restrict__ A, const unsigned* __restrict__ B,
              void* __restrict__ C, int N, int K)
{
    extern __shared__ unsigned gsm[];
    unsigned* As = gsm;                   // [STG][TILE_U]
    unsigned* Bs = gsm + STG * TILE_U;    // [STG][TILE_U]

    const int bm   = blockIdx.y << 7;
    const int bn   = blockIdx.x << 7;
    const int tid  = threadIdx.x;
    const int lane = tid & 31;
    const int wid  = tid >> 5;
    const int wm   = wid >> 2;     // 0..1
    const int wn   = wid & 3;      // 0..3
    const int g    = lane >> 2;    // 0..7
    const int t4   = lane & 3;     // 0..3

    const int r0 = tid >> 2;             // 0..63
    const int c0 = (tid & 3) << 2;       // 0,4,8,12
    const unsigned* Ag0 = A + (size_t)(bm + r0)      * K + c0;
    const unsigned* Ag1 = A + (size_t)(bm + r0 + 64) * K + c0;
    const unsigned* Bg0 = B + (size_t)(bn + r0)      * K + c0;
    const unsigned* Bg1 = B + (size_t)(bn + r0 + 64) * K + c0;

    const uint32_t asb = smem_u32(As) + (r0 * BKS + c0) * 4;
    const uint32_t bsb = smem_u32(Bs) + (r0 * BKS + c0) * 4;
    const uint32_t row64 = 64 * BKS * 4;
    const uint32_t stgB  = TILE_U * 4;

    float acc[4][4][4];
#pragma unroll
    for (int mt = 0; mt < 4; mt++)
#pragma unroll
        for (int nt = 0; nt < 4; nt++)
#pragma unroll
            for (int r = 0; r < 4; r++) acc[mt][nt][r] = 0.f;

    const int NT = K >> 4;   // 64 for K=1024

    // ---- prologue: stage tiles 0..2 into bufs 0..2, one group each ----
#pragma unroll
    for (int s = 0; s < STG - 1; s++) {
        const int ko = s << 4;
        const uint32_t off = s * stgB;
        cp16(asb + off,         Ag0 + ko);
        cp16(asb + off + row64, Ag1 + ko);
        cp16(bsb + off,         Bg0 + ko);
        cp16(bsb + off + row64, Bg1 + ko);
        CP_COMMIT();
    }

    for (int kt = 0; kt < NT; kt++) {
        CP_WAIT2();            // tile kt landed (2 newest groups may be open)
        __syncthreads();       // all warps done reading buf (kt-1)&3

        if (kt + STG - 1 < NT) {
            const int ko = (kt + STG - 1) << 4;
            const uint32_t off = ((kt + STG - 1) & (STG - 1)) * stgB;
            cp16(asb + off,         Ag0 + ko);
            cp16(asb + off + row64, Ag1 + ko);
            cp16(bsb + off,         Bg0 + ko);
            cp16(bsb + off + row64, Bg1 + ko);
        }
        CP_COMMIT();           // unconditional: keeps wait_group 2 exact

        const unsigned* as = As + (kt & (STG - 1)) * TILE_U;
        const unsigned* bs = Bs + (kt & (STG - 1)) * TILE_U;

#pragma unroll
        for (int ks = 0; ks < 2; ks++) {
            const int kb = ks * 8;
            unsigned af[4][4], bf[4][2];
#pragma unroll
            for (int mt = 0; mt < 4; mt++) {
                const int row = wm * 64 + mt * 16 + g;
                af[mt][0] = as[ row      * BKS + kb + t4];
                af[mt][1] = as[(row + 8) * BKS + kb + t4];
                af[mt][2] = as[ row      * BKS + kb + t4 + 4];
                af[mt][3] = as[(row + 8) * BKS + kb + t4 + 4];
            }
#pragma unroll
            for (int nt = 0; nt < 4; nt++) {
                const int nr = wn * 32 + nt * 8 + g;
                bf[nt][0] = bs[nr * BKS + kb + t4];
                bf[nt][1] = bs[nr * BKS + kb + t4 + 4];
            }
#pragma unroll
            for (int mt = 0; mt < 4; mt++)
#pragma unroll
                for (int nt = 0; nt < 4; nt++)
                    mma8(acc[mt][nt], af[mt], bf[nt]);
        }
    }

    if (TF32OUT) {
        // Q columns (bn < 1024) pre-scaled by 1/sqrt(D) = 0.125
        const float s = (bn < 1024) ? 0.125f : 1.0f;
        unsigned* Cu = (unsigned*)C;
#pragma unroll
        for (int mt = 0; mt < 4; mt++) {
            const int row = bm + wm * 64 + mt * 16 + g;
#pragma unroll
            for (int nt = 0; nt < 4; nt++) {
                const int col = bn + wn * 32 + nt * 8 + 2 * t4;
                *(uint2*)(Cu + (size_t)row * N + col) =
                    make_uint2(f2tf(acc[mt][nt][0] * s), f2tf(acc[mt][nt][1] * s));
                *(uint2*)(Cu + (size_t)(row + 8) * N + col) =
                    make_uint2(f2tf(acc[mt][nt][2] * s), f2tf(acc[mt][nt][3] * s));
            }
        }
    } else {
        float* Cf = (float*)C;
#pragma unroll
        for (int mt = 0; mt < 4; mt++) {
            const int row = bm + wm * 64 + mt * 16 + g;
#pragma unroll
            for (int nt = 0; nt < 4; nt++) {
                const int col = bn + wn * 32 + nt * 8 + 2 * t4;
                *(float2*)(Cf + (size_t)row * N + col) =
                    make_float2(acc[mt][nt][0], acc[mt][nt][1]);
                *(float2*)(Cf + (size_t)(row + 8) * N + col) =
                    make_float2(acc[mt][nt][2], acc[mt][nt][3]);
            }
        }
    }
}

__global__ __launch_bounds__(256, 2)
void qkv_gemm_kernel()
{
    gemm4_nt<true>(g_x32, g_w1, g_qkv, QKVN, LL);
}

__global__ __launch_bounds__(256, 2)
void out_gemm_kernel(float* __restrict__ out)
{
    gemm4_nt<false>(g_attn, g_w2, out, LL, LL);
}

// ---------------------------------------------------------------------------
// Flash attention, causal, TF32 tensor cores (R14 config, unchanged):
// double-buffered K/V via cp.async prefetch (wait_group 1); per-block
// compute (~128 MMAs/warp) >> mem latency so depth-2 suffices here.
// ---------------------------------------------------------------------------
#define QTILE 128
#define AST 68
#define VST 72
#define KVSZ (64 * AST + 64 * VST)                 // 8960 u32 per stage
#define ATTN_SMEM ((QTILE * AST + 2 * KVSZ) * 4)   // 106496 B

__global__ __launch_bounds__(256, 2)
void attn_kernel()
{
    extern __shared__ unsigned sm[];
    unsigned* Qs = sm;                                // [128][68], tf32 (pre-scaled)

    const int qb   = gridDim.x - 1 - blockIdx.x;      // heavy first
    const int h    = blockIdx.y;
    const int b    = blockIdx.z;
    const int hk   = h >> 2;
    const int tid  = threadIdx.x;
    const int lane = tid & 31;
    const int w    = tid >> 5;
    const int g    = lane >> 2;
    const int t4   = lane & 3;
    const int R0   = 16 * w + g;
    const int gR0  = qb * QTILE + R0;

    const uint32_t qs_b  = smem_u32(Qs);
    const uint32_t kv0_b = qs_b + QTILE * AST * 4;

    auto stage_kv = [&](int buf, int kb) {
        const unsigned* kbase = g_qkv + (size_t)(b * SS + kb * 64) * QKVN
                                + HH * DD + hk * DD;
        const uint32_t ks_b = kv0_b + buf * (KVSZ * 4);
        const uint32_t vs_b = ks_b + 64 * AST * 4;
#pragma unroll
        for (int i = 0; i < 4; i++) {
            const int e = tid + i * 256;
            const int r = e >> 4, c = (e & 15) << 2;
            const unsigned* p = kbase + (size_t)r * QKVN + c;
            cp16(ks_b + (r * AST + c) * 4, p);
            cp16(vs_b + (r * VST + c) * 4, p + HKK * DD);
        }
    };

    // ---- group 0: Q tile + KV block 0 ----
    {
        const unsigned* qbase = g_qkv + (size_t)(b * SS + qb * QTILE) * QKVN + h * DD;
#pragma unroll
        for (int i = 0; i < 8; i++) {
            const int e = tid + i * 256;
            const int r = e >> 4, c = (e & 15) << 2;
            cp16(qs_b + (r * AST + c) * 4, qbase + (size_t)r * QKVN + c);
        }
        stage_kv(0, 0);
        CP_COMMIT();
    }

    float m0 = -1e30f, m1 = -1e30f, l0 = 0.f, l1 = 0.f;
    float oacc[8][4];
#pragma unroll
    for (int nt = 0; nt < 8; nt++)
#pragma unroll
        for (int r = 0; r < 4; r++) oacc[nt][r] = 0.f;

    const int kb_max = 2 * qb + 1;
    for (int kb = 0; kb <= kb_max; kb++) {
        if (kb < kb_max) {
            stage_kv((kb + 1) & 1, kb + 1);
            CP_COMMIT();
            CP_WAIT1();
        } else {
            CP_WAIT0();
        }
        __syncthreads();

        const unsigned* Ks = sm + QTILE * AST + (kb & 1) * KVSZ;
        const unsigned* Vs = Ks + 64 * AST;

        const bool active = (kb * 64 <= qb * QTILE + 16 * w + 15);
        if (active) {
            float sacc[8][4];
#pragma unroll
            for (int nt = 0; nt < 8; nt++)
#pragma unroll
                for (int r = 0; r < 4; r++) sacc[nt][r] = 0.f;

#pragma unroll
            for (int kk = 0; kk < 8; kk++) {
                const int kp = kk * 8;
                unsigned af[4];
                af[0] = Qs[ R0      * AST + kp + t4];
                af[1] = Qs[(R0 + 8) * AST + kp + t4];
                af[2] = Qs[ R0      * AST + kp + t4 + 4];
                af[3] = Qs[(R0 + 8) * AST + kp + t4 + 4];
#pragma unroll
                for (int nt = 0; nt < 8; nt++) {
                    unsigned bf[2];
                    bf[0] = Ks[(nt * 8 + g) * AST + kp + t4];
                    bf[1] = Ks[(nt * 8 + g) * AST + kp + t4 + 4];
                    mma8(sacc[nt], af, bf);
                }
            }

            if (kb * 64 + 63 > qb * QTILE + 16 * w) {
#pragma unroll
                for (int nt = 0; nt < 8; nt++) {
                    const int cc = kb * 64 + nt * 8 + 2 * t4;
                    if (cc     > gR0)     sacc[nt][0] = -1e30f;
                    if (cc + 1 > gR0)     sacc[nt][1] = -1e30f;
                    if (cc     > gR0 + 8) sacc[nt][2] = -1e30f;
                    if (cc + 1 > gR0 + 8) sacc[nt][3] = -1e30f;
                }
            }

            float mx0 = -1e30f, mx1 = -1e30f;
#pragma unroll
            for (int nt = 0; nt < 8; nt++) {
                mx0 = fmaxf(mx0, fmaxf(sacc[nt][0], sacc[nt][1]));
                mx1 = fmaxf(mx1, fmaxf(sacc[nt][2], sacc[nt][3]));
            }
            mx0 = fmaxf(mx0, __shfl_xor_sync(0xffffffffu, mx0, 1));
            mx0 = fmaxf(mx0, __shfl_xor_sync(0xffffffffu, mx0, 2));
            mx1 = fmaxf(mx1, __shfl_xor_sync(0xffffffffu, mx1, 1));
            mx1 = fmaxf(mx1, __shfl_xor_sync(0xffffffffu, mx1, 2));

            const float mn0 = fmaxf(m0, mx0);
            const float mn1 = fmaxf(m1, mx1);
            float sum0 = 0.f, sum1 = 0.f;
#pragma unroll
            for (int nt = 0; nt < 8; nt++) {
                sacc[nt][0] = __expf(sacc[nt][0] - mn0);
                sacc[nt][1] = __expf(sacc[nt][1] - mn0);
                sacc[nt][2] = __expf(sacc[nt][2] - mn1);
                sacc[nt][3] = __expf(sacc[nt][3] - mn1);
                sum0 += sacc[nt][0] + sacc[nt][1];
                sum1 += sacc[nt][2] + sacc[nt][3];
            }
            sum0 += __shfl_xor_sync(0xffffffffu, sum0, 1);
            sum0 += __shfl_xor_sync(0xffffffffu, sum0, 2);
            sum1 += __shfl_xor_sync(0xffffffffu, sum1, 1);
            sum1 += __shfl_xor_sync(0xffffffffu, sum1, 2);

            const float a0 = __expf(m0 - mn0);
            const float a1 = __expf(m1 - mn1);
            l0 = l0 * a0 + sum0;  m0 = mn0;
            l1 = l1 * a1 + sum1;  m1 = mn1;
#pragma unroll
            for (int nt = 0; nt < 8; nt++) {
                oacc[nt][0] *= a0; oacc[nt][1] *= a0;
                oacc[nt][2] *= a1; oacc[nt][3] *= a1;
            }

            const int sA = (lane & ~3) | (t4 >> 1);
            const int sB = sA + 2;
            const bool odd = (t4 & 1);
#pragma unroll
            for (int kk = 0; kk < 8; kk++) {
                float v0A = __shfl_sync(0xffffffffu, sacc[kk][0], sA);
                float v1A = __shfl_sync(0xffffffffu, sacc[kk][1], sA);
                float v2A = __shfl_sync(0xffffffffu, sacc[kk][2], sA);
                float v3A = __shfl_sync(0xffffffffu, sacc[kk][3], sA);
                float v0B = __shfl_sync(0xffffffffu, sacc[kk][0], sB);
                float v1B = __shfl_sync(0xffffffffu, sacc[kk][1], sB);
                float v2B = __shfl_sync(0xffffffffu, sacc[kk][2], sB);
                float v3B = __shfl_sync(0xffffffffu, sacc[kk][3], sB);
                unsigned af[4];
                af[0] = f2tf(odd ? v1A : v0A);
                af[1] = f2tf(odd ? v3A : v2A);
                af[2] = f2tf(odd ? v1B : v0B);
                af[3] = f2tf(odd ? v3B : v2B);
                const int kp = kk * 8;
#pragma unroll
                for (int nt = 0; nt < 8; nt++) {
                    unsigned bf[2];
                    bf[0] = Vs[(kp + t4)     * VST + nt * 8 + g];
                    bf[1] = Vs[(kp + t4 + 4) * VST + nt * 8 + g];
                    mma8(oacc[nt], af, bf);
                }
            }
        }
        __syncthreads();
    }

    const float inv0 = 1.f / l0;
    const float inv1 = 1.f / l1;
    unsigned* ob = g_attn + (size_t)(b * SS + qb * QTILE) * LL + h * DD;
#pragma unroll
    for (int nt = 0; nt < 8; nt++) {
        const int cc = nt * 8 + 2 * t4;
        *(uint2*)(ob + (size_t)R0 * LL + cc) =
            make_uint2(f2tf(oacc[nt][0] * inv0), f2tf(oacc[nt][1] * inv0));
        *(uint2*)(ob + (size_t)(R0 + 8) * LL + cc) =
            make_uint2(f2tf(oacc[nt][2] * inv1), f2tf(oacc[nt][3] * inv1));
    }
}

// ---------------------------------------------------------------------------
extern "C" void kernel_launch(void* const* d_in, const int* in_sizes, int n_in,
                              void* d_out, int out_size)
{
    const float* x = nullptr;
    const float* w_qkv = nullptr;
    const float* w_out = nullptr;
    for (int i = 0; i < n_in; i++) {
        if      (in_sizes[i] == 4194304) x     = (const float*)d_in[i];
        else if (in_sizes[i] == 3670016) w_qkv = (const float*)d_in[i];
        else if (in_sizes[i] == 1048576) w_out = (const float*)d_in[i];
    }
    float* out = (float*)d_out;

    static bool attr_set = false;
    if (!attr_set) {
        cudaFuncSetAttribute(attn_kernel,
                             cudaFuncAttributeMaxDynamicSharedMemorySize,
                             ATTN_SMEM);
        cudaFuncSetAttribute(qkv_gemm_kernel,
                             cudaFuncAttributeMaxDynamicSharedMemorySize,
                             GEMM_SMEM);
        cudaFuncSetAttribute(out_gemm_kernel,
                             cudaFuncAttributeMaxDynamicSharedMemorySize,
                             GEMM_SMEM);
        attr_set = true;
    }

    unsigned* d_x32; cudaGetSymbolAddress((void**)&d_x32, g_x32);
    unsigned* d_w1;  cudaGetSymbolAddress((void**)&d_w1,  g_w1);
    unsigned* d_w2;  cudaGetSymbolAddress((void**)&d_w2,  g_w2);

    // 0) one-time tf32 conversion of inputs
    cvt_kernel<<<(MROWS * LL) / 1024, 256>>>(x, d_x32);
    cvt_kernel<<<(QKVN  * LL) / 1024, 256>>>(w_qkv, d_w1);
    cvt_kernel<<<(LL    * LL) / 1024, 256>>>(w_out, d_w2);

    // 1) fused QKV projection -> g_qkv (tf32, Q pre-scaled): 4-stage pipeline
    qkv_gemm_kernel<<<dim3(QKVN / 128, MROWS / 128), 256, GEMM_SMEM>>>();

    // 2) causal GQA flash attention -> g_attn (tf32), double-buffered KV
    attn_kernel<<<dim3(SS / QTILE, HH, BB), 256, ATTN_SMEM>>>();

    // 3) output projection -> out (fp32): 4-stage pipeline
    out_gemm_kernel<<<dim3(LL / 128, MROWS / 128), 256, GEMM_SMEM>>>(out);
}

// round 16
// speedup vs baseline: 1.7963x; 1.7770x over previous
#include <cuda_runtime.h>
#include <cuda_fp16.h>
#include <math.h>
#include <stdint.h>

// Problem constants
#define BB   2
#define SS   2048
#define LL   1024
#define HH   16
#define HKK  4
#define DD   64
#define MROWS (BB*SS)            // 4096
#define QKVN  ((HH + 2*HKK)*DD)  // 1536

// Scratch (allocation-free rule: __device__ globals). All fp16 storage.
__device__ __half g_xh  [MROWS * LL];     // x   -> fp16
__device__ __half g_w1h [QKVN * LL];      // w_qkv[0:1536] -> fp16
__device__ __half g_w2h [LL * LL];        // w_out -> fp16
__device__ __half g_qkv [MROWS * QKVN];   // qkv proj (Q cols pre-scaled), fp16
__device__ __half g_attn[MROWS * LL];     // attention output, fp16

// ---------------------------------------------------------------------------
// helpers
// ---------------------------------------------------------------------------
__device__ __forceinline__ unsigned packh2(float lo, float hi) {
    half2 h = __floats2half2_rn(lo, hi);
    return *(unsigned*)&h;
}

// D += A*B, m16n8k16 fp16 inputs, fp32 accumulate.
__device__ __forceinline__ void mma16(float* c, const unsigned* a, const unsigned* b) {
    asm volatile(
        "mma.sync.aligned.m16n8k16.row.col.f32.f16.f16.f32 "
        "{%0,%1,%2,%3}, {%4,%5,%6,%7}, {%8,%9}, {%0,%1,%2,%3};"
        : "+f"(c[0]), "+f"(c[1]), "+f"(c[2]), "+f"(c[3])
        : "r"(a[0]), "r"(a[1]), "r"(a[2]), "r"(a[3]),
          "r"(b[0]), "r"(b[1]));
}

__device__ __forceinline__ void ldsm4t(unsigned& r0, unsigned& r1,
                                       unsigned& r2, unsigned& r3, uint32_t a) {
    asm volatile("ldmatrix.sync.aligned.m8n8.x4.trans.shared.b16 {%0,%1,%2,%3}, [%4];"
                 : "=r"(r0), "=r"(r1), "=r"(r2), "=r"(r3) : "r"(a));
}

__device__ __forceinline__ uint32_t smem_u32(const void* p) {
    uint32_t a;
    asm("{ .reg .u64 t; cvta.to.shared.u64 t, %1; cvt.u32.u64 %0, t; }"
        : "=r"(a) : "l"(p));
    return a;
}

__device__ __forceinline__ void cp16(uint32_t dst, const void* src) {
    asm volatile("cp.async.cg.shared.global [%0], [%1], 16;"
                 :: "r"(dst), "l"(src));
}
#define CP_COMMIT() asm volatile("cp.async.commit_group;" ::: "memory")
#define CP_WAIT0()  asm volatile("cp.async.wait_group 0;"  ::: "memory")
#define CP_WAIT1()  asm volatile("cp.async.wait_group 1;"  ::: "memory")
#define CP_WAIT2()  asm volatile("cp.async.wait_group 2;"  ::: "memory")

// ---------------------------------------------------------------------------
// One-time fp32 -> fp16 conversion (rn)
// ---------------------------------------------------------------------------
__global__ __launch_bounds__(256)
void cvt_kernel(const float* __restrict__ src, __half* __restrict__ dst)
{
    const int i = (blockIdx.x * 256 + threadIdx.x) * 4;
    float4 v = *(const float4*)(src + i);
    uint2 o = make_uint2(packh2(v.x, v.y), packh2(v.z, v.w));
    *(uint2*)((char*)dst + (size_t)i * 2) = o;
}

// ---------------------------------------------------------------------------
// FP16 tensor-core GEMM (NT): C = A * B^T, A/B fp16, fp32 accumulate.
// 128x128 CTA, BK=32 f16 per kt (2 x k16), 256 threads, warps 2(M)x4(N)
// -> 64x32 warp tiles. 4-stage cp.async pipeline. Smem rows: 16 data words
// + 4 pad = 20 words (banks 20g+t4 all distinct mod 32).
// ---------------------------------------------------------------------------
#define RW   20                               // row stride in u32 words
#define TILE_U (128 * RW)                     // 2560 u32 per matrix per stage
#define STG  4
#define GEMM_SMEM (STG * 2 * TILE_U * 4)      // 81920 B -> 2 CTAs/SM

// OUTM: 0 = fp32 out, 1 = fp16 out with Q-prescale (bn < 1024 -> *0.125)
template <int OUTM>
__device__ __forceinline__
void gemm16_nt(const __half* __restrict__ A, const __half* __restrict__ B,
               void* __restrict__ C, int N, int K)
{
    extern __shared__ unsigned gsm[];
    unsigned* As = gsm;                   // [STG][TILE_U]
    unsigned* Bs = gsm + STG * TILE_U;

    const int bm   = blockIdx.y << 7;
    const int bn   = blockIdx.x << 7;
    const int tid  = threadIdx.x;
    const int lane = tid & 31;
    const int wid  = tid >> 5;
    const int wm   = wid >> 2;     // 0..1
    const int wn   = wid & 3;      // 0..3
    const int g    = lane >> 2;    // 0..7
    const int t4   = lane & 3;     // 0..3

    // staging map: r = tid>>1 (0..127), q = tid&1 -> word offsets q*8, q*8+4
    const int r  = tid >> 1;
    const int q  = tid & 1;
    const __half* Ag = A + (size_t)(bm + r) * K + q * 16;
    const __half* Bg = B + (size_t)(bn + r) * K + q * 16;
    const uint32_t asb = smem_u32(As) + (r * RW + q * 8) * 4;
    const uint32_t bsb = smem_u32(Bs) + (r * RW + q * 8) * 4;
    const uint32_t stgB = TILE_U * 4;

    float acc[4][4][4];
#pragma unroll
    for (int mt = 0; mt < 4; mt++)
#pragma unroll
        for (int nt = 0; nt < 4; nt++)
#pragma unroll
            for (int rr = 0; rr < 4; rr++) acc[mt][nt][rr] = 0.f;

    const int NT = K >> 5;   // 32 for K=1024 (32 f16 per kt)

    // prologue: stage tiles 0..2
#pragma unroll
    for (int s = 0; s < STG - 1; s++) {
        const int ko = s << 5;
        const uint32_t off = s * stgB;
        cp16(asb + off,      Ag + ko);
        cp16(asb + off + 16, Ag + ko + 8);
        cp16(bsb + off,      Bg + ko);
        cp16(bsb + off + 16, Bg + ko + 8);
        CP_COMMIT();
    }

    for (int kt = 0; kt < NT; kt++) {
        CP_WAIT2();
        __syncthreads();

        if (kt + STG - 1 < NT) {
            const int ko = (kt + STG - 1) << 5;
            const uint32_t off = ((kt + STG - 1) & (STG - 1)) * stgB;
            cp16(asb + off,      Ag + ko);
            cp16(asb + off + 16, Ag + ko + 8);
            cp16(bsb + off,      Bg + ko);
            cp16(bsb + off + 16, Bg + ko + 8);
        }
        CP_COMMIT();

        const unsigned* as = As + (kt & (STG - 1)) * TILE_U;
        const unsigned* bs = Bs + (kt & (STG - 1)) * TILE_U;

#pragma unroll
        for (int ks = 0; ks < 2; ks++) {
            const int kb = ks * 8;
            unsigned af[4][4], bf[4][2];
#pragma unroll
            for (int mt = 0; mt < 4; mt++) {
                const int row = wm * 64 + mt * 16 + g;
                af[mt][0] = as[ row      * RW + kb + t4];
                af[mt][1] = as[(row + 8) * RW + kb + t4];
                af[mt][2] = as[ row      * RW + kb + t4 + 4];
                af[mt][3] = as[(row + 8) * RW + kb + t4 + 4];
            }
#pragma unroll
            for (int nt = 0; nt < 4; nt++) {
                const int nr = wn * 32 + nt * 8 + g;
                bf[nt][0] = bs[nr * RW + kb + t4];
                bf[nt][1] = bs[nr * RW + kb + t4 + 4];
            }
#pragma unroll
            for (int mt = 0; mt < 4; mt++)
#pragma unroll
                for (int nt = 0; nt < 4; nt++)
                    mma16(acc[mt][nt], af[mt], bf[nt]);
        }
    }

    if (OUTM == 1) {
        const float s = (bn < 1024) ? 0.125f : 1.0f;
        __half* Ch = (__half*)C;
#pragma unroll
        for (int mt = 0; mt < 4; mt++) {
            const int row = bm + wm * 64 + mt * 16 + g;
#pragma unroll
            for (int nt = 0; nt < 4; nt++) {
                const int col = bn + wn * 32 + nt * 8 + 2 * t4;
                *(unsigned*)(Ch + (size_t)row * N + col) =
                    packh2(acc[mt][nt][0] * s, acc[mt][nt][1] * s);
                *(unsigned*)(Ch + (size_t)(row + 8) * N + col) =
                    packh2(acc[mt][nt][2] * s, acc[mt][nt][3] * s);
            }
        }
    } else {
        float* Cf = (float*)C;
#pragma unroll
        for (int mt = 0; mt < 4; mt++) {
            const int row = bm + wm * 64 + mt * 16 + g;
#pragma unroll
            for (int nt = 0; nt < 4; nt++) {
                const int col = bn + wn * 32 + nt * 8 + 2 * t4;
                *(float2*)(Cf + (size_t)row * N + col) =
                    make_float2(acc[mt][nt][0], acc[mt][nt][1]);
                *(float2*)(Cf + (size_t)(row + 8) * N + col) =
                    make_float2(acc[mt][nt][2], acc[mt][nt][3]);
            }
        }
    }
}

__global__ __launch_bounds__(256, 2)
void qkv_gemm_kernel()
{
    gemm16_nt<1>(g_xh, g_w1h, g_qkv, QKVN, LL);
}

__global__ __launch_bounds__(256, 2)
void out_gemm_kernel(float* __restrict__ out)
{
    gemm16_nt<0>(g_attn, g_w2h, out, LL, LL);
}

// ---------------------------------------------------------------------------
// Flash attention, causal, FP16 tensor cores (m16n8k16, fp32 accum).
// grid = (S/128, H, B) qb reversed; 256 threads = 8 warps, warp w owns rows
// 16w..16w+15. Q/K fragments direct LDS.32 (stride 72 f16 = 36 words, banks
// 4g+t4 conflict-free). V row-major, B-fragments via ldmatrix.x4.trans.
// P: QK C-fragment IS the k16 A-fragment -> just 4 half2 packs per k16,
// zero shuffles. Double-buffered KV via cp.async.
// ---------------------------------------------------------------------------
#define QTILE 128
#define ASTW  36                              // row stride in u32 words (72 f16)
#define QW    (QTILE * ASTW)                  // 4608 words
#define KVW   (2 * 64 * ASTW)                 // K + V per stage = 4608 words
#define ATTN_SMEM ((QW + 2 * KVW) * 4)        // 55296 B

__global__ __launch_bounds__(256, 2)
void attn_kernel()
{
    extern __shared__ unsigned sm[];          // word-addressed fp16 tiles

    const int qb   = gridDim.x - 1 - blockIdx.x;   // heavy first
    const int h    = blockIdx.y;
    const int b    = blockIdx.z;
    const int hk   = h >> 2;
    const int tid  = threadIdx.x;
    const int lane = tid & 31;
    const int w    = tid >> 5;
    const int g    = lane >> 2;
    const int t4   = lane & 3;
    const int R0   = 16 * w + g;
    const int gR0  = qb * QTILE + R0;

    const uint32_t smb  = smem_u32(sm);

    auto stage_kv = [&](int buf, int kb) {
        const __half* kbase = g_qkv + (size_t)(b * SS + kb * 64) * QKVN
                              + HH * DD + hk * DD;
        const uint32_t ks_b = smb + (QW + buf * KVW) * 4;
        const uint32_t vs_b = ks_b + 64 * ASTW * 4;
#pragma unroll
        for (int i = 0; i < 2; i++) {
            const int e  = tid + i * 256;
            const int r  = e >> 3;             // 0..63
            const int c8 = (e & 7) * 8;        // f16 col
            const __half* p = kbase + (size_t)r * QKVN + c8;
            cp16(ks_b + (r * ASTW + c8 / 2) * 4, p);
            cp16(vs_b + (r * ASTW + c8 / 2) * 4, p + HKK * DD);
        }
    };

    // ---- group 0: Q tile + KV block 0 ----
    {
        const __half* qbase = g_qkv + (size_t)(b * SS + qb * QTILE) * QKVN + h * DD;
#pragma unroll
        for (int i = 0; i < 4; i++) {
            const int e  = tid + i * 256;
            const int r  = e >> 3;             // 0..127
            const int c8 = (e & 7) * 8;
            cp16(smb + (r * ASTW + c8 / 2) * 4, qbase + (size_t)r * QKVN + c8);
        }
        stage_kv(0, 0);
        CP_COMMIT();
    }

    float m0 = -1e30f, m1 = -1e30f, l0 = 0.f, l1 = 0.f;
    float oacc[8][4];
#pragma unroll
    for (int nt = 0; nt < 8; nt++)
#pragma unroll
        for (int r = 0; r < 4; r++) oacc[nt][r] = 0.f;

    const int kb_max = 2 * qb + 1;
    for (int kb = 0; kb <= kb_max; kb++) {
        if (kb < kb_max) {
            stage_kv((kb + 1) & 1, kb + 1);
            CP_COMMIT();
            CP_WAIT1();
        } else {
            CP_WAIT0();
        }
        __syncthreads();

        const unsigned* Qs = sm;
        const unsigned* Ks = sm + QW + (kb & 1) * KVW;
        const uint32_t  vs_b = smb + (QW + (kb & 1) * KVW + 64 * ASTW) * 4;

        const bool active = (kb * 64 <= qb * QTILE + 16 * w + 15);
        if (active) {
            // ---- S = Q K^T : 4 k16 groups x 8 n-tiles ----
            float sacc[8][4];
#pragma unroll
            for (int nt = 0; nt < 8; nt++)
#pragma unroll
                for (int r = 0; r < 4; r++) sacc[nt][r] = 0.f;

#pragma unroll
            for (int kk = 0; kk < 4; kk++) {
                const int kw = kk * 8;
                unsigned af[4];
                af[0] = Qs[ R0      * ASTW + kw + t4];
                af[1] = Qs[(R0 + 8) * ASTW + kw + t4];
                af[2] = Qs[ R0      * ASTW + kw + t4 + 4];
                af[3] = Qs[(R0 + 8) * ASTW + kw + t4 + 4];
#pragma unroll
                for (int nt = 0; nt < 8; nt++) {
                    unsigned bf[2];
                    bf[0] = Ks[(nt * 8 + g) * ASTW + kw + t4];
                    bf[1] = Ks[(nt * 8 + g) * ASTW + kw + t4 + 4];
                    mma16(sacc[nt], af, bf);
                }
            }

            // ---- causal mask ----
            if (kb * 64 + 63 > qb * QTILE + 16 * w) {
#pragma unroll
                for (int nt = 0; nt < 8; nt++) {
                    const int cc = kb * 64 + nt * 8 + 2 * t4;
                    if (cc     > gR0)     sacc[nt][0] = -1e30f;
                    if (cc + 1 > gR0)     sacc[nt][1] = -1e30f;
                    if (cc     > gR0 + 8) sacc[nt][2] = -1e30f;
                    if (cc + 1 > gR0 + 8) sacc[nt][3] = -1e30f;
                }
            }

            // ---- online softmax (fp32, unchanged) ----
            float mx0 = -1e30f, mx1 = -1e30f;
#pragma unroll
            for (int nt = 0; nt < 8; nt++) {
                mx0 = fmaxf(mx0, fmaxf(sacc[nt][0], sacc[nt][1]));
                mx1 = fmaxf(mx1, fmaxf(sacc[nt][2], sacc[nt][3]));
            }
            mx0 = fmaxf(mx0, __shfl_xor_sync(0xffffffffu, mx0, 1));
            mx0 = fmaxf(mx0, __shfl_xor_sync(0xffffffffu, mx0, 2));
            mx1 = fmaxf(mx1, __shfl_xor_sync(0xffffffffu, mx1, 1));
            mx1 = fmaxf(mx1, __shfl_xor_sync(0xffffffffu, mx1, 2));

            const float mn0 = fmaxf(m0, mx0);
            const float mn1 = fmaxf(m1, mx1);
            float sum0 = 0.f, sum1 = 0.f;
#pragma unroll
            for (int nt = 0; nt < 8; nt++) {
                sacc[nt][0] = __expf(sacc[nt][0] - mn0);
                sacc[nt][1] = __expf(sacc[nt][1] - mn0);
                sacc[nt][2] = __expf(sacc[nt][2] - mn1);
                sacc[nt][3] = __expf(sacc[nt][3] - mn1);
                sum0 += sacc[nt][0] + sacc[nt][1];
                sum1 += sacc[nt][2] + sacc[nt][3];
            }
            sum0 += __shfl_xor_sync(0xffffffffu, sum0, 1);
            sum0 += __shfl_xor_sync(0xffffffffu, sum0, 2);
            sum1 += __shfl_xor_sync(0xffffffffu, sum1, 1);
            sum1 += __shfl_xor_sync(0xffffffffu, sum1, 2);

            const float a0 = __expf(m0 - mn0);
            const float a1 = __expf(m1 - mn1);
            l0 = l0 * a0 + sum0;  m0 = mn0;
            l1 = l1 * a1 + sum1;  m1 = mn1;
#pragma unroll
            for (int nt = 0; nt < 8; nt++) {
                oacc[nt][0] *= a0; oacc[nt][1] *= a0;
                oacc[nt][2] *= a1; oacc[nt][3] *= a1;
            }

            // ---- O += P*V : C-frag == k16 A-frag (just pack), V via ldmatrix.trans
#pragma unroll
            for (int kk = 0; kk < 4; kk++) {
                unsigned af[4];
                af[0] = packh2(sacc[2*kk    ][0], sacc[2*kk    ][1]);
                af[1] = packh2(sacc[2*kk    ][2], sacc[2*kk    ][3]);
                af[2] = packh2(sacc[2*kk + 1][0], sacc[2*kk + 1][1]);
                af[3] = packh2(sacc[2*kk + 1][2], sacc[2*kk + 1][3]);

                const int vrow = kk * 16 + (lane & 7) + 8 * ((lane >> 3) & 1);
                const int vcol0 = 8 * (lane >> 4);
#pragma unroll
                for (int j = 0; j < 4; j++) {
                    unsigned b0, b1, b2, b3;
                    const uint32_t addr =
                        vs_b + (vrow * ASTW * 2 + (j * 16 + vcol0)) * 2;
                    ldsm4t(b0, b1, b2, b3, addr);
                    unsigned bl[2] = {b0, b1};
                    mma16(oacc[2*j], af, bl);
                    unsigned bh[2] = {b2, b3};
                    mma16(oacc[2*j + 1], af, bh);
                }
            }
        }
        __syncthreads();
    }

    // ---- normalize + store fp16 (head-major [b,s,h,d]) ----
    const float inv0 = 1.f / l0;
    const float inv1 = 1.f / l1;
    __half* ob = g_attn + (size_t)(b * SS + qb * QTILE) * LL + h * DD;
#pragma unroll
    for (int nt = 0; nt < 8; nt++) {
        const int cc = nt * 8 + 2 * t4;
        *(unsigned*)(ob + (size_t)R0 * LL + cc) =
            packh2(oacc[nt][0] * inv0, oacc[nt][1] * inv0);
        *(unsigned*)(ob + (size_t)(R0 + 8) * LL + cc) =
            packh2(oacc[nt][2] * inv1, oacc[nt][3] * inv1);
    }
}

// ---------------------------------------------------------------------------
extern "C" void kernel_launch(void* const* d_in, const int* in_sizes, int n_in,
                              void* d_out, int out_size)
{
    const float* x = nullptr;
    const float* w_qkv = nullptr;
    const float* w_out = nullptr;
    for (int i = 0; i < n_in; i++) {
        if      (in_sizes[i] == 4194304) x     = (const float*)d_in[i];
        else if (in_sizes[i] == 3670016) w_qkv = (const float*)d_in[i];
        else if (in_sizes[i] == 1048576) w_out = (const float*)d_in[i];
    }
    float* out = (float*)d_out;

    static bool attr_set = false;
    if (!attr_set) {
        cudaFuncSetAttribute(attn_kernel,
                             cudaFuncAttributeMaxDynamicSharedMemorySize,
                             ATTN_SMEM);
        cudaFuncSetAttribute(qkv_gemm_kernel,
                             cudaFuncAttributeMaxDynamicSharedMemorySize,
                             GEMM_SMEM);
        cudaFuncSetAttribute(out_gemm_kernel,
                             cudaFuncAttributeMaxDynamicSharedMemorySize,
                             GEMM_SMEM);
        attr_set = true;
    }

    __half* d_xh;  cudaGetSymbolAddress((void**)&d_xh,  g_xh);
    __half* d_w1h; cudaGetSymbolAddress((void**)&d_w1h, g_w1h);
    __half* d_w2h; cudaGetSymbolAddress((void**)&d_w2h, g_w2h);

    // 0) one-time fp32 -> fp16 conversion of inputs
    cvt_kernel<<<(MROWS * LL) / 1024, 256>>>(x, d_xh);
    cvt_kernel<<<(QKVN  * LL) / 1024, 256>>>(w_qkv, d_w1h);
    cvt_kernel<<<(LL    * LL) / 1024, 256>>>(w_out, d_w2h);

    // 1) fused QKV projection -> g_qkv (fp16, Q pre-scaled)
    qkv_gemm_kernel<<<dim3(QKVN / 128, MROWS / 128), 256, GEMM_SMEM>>>();

    // 2) causal GQA flash attention -> g_attn (fp16)
    attn_kernel<<<dim3(SS / QTILE, HH, BB), 256, ATTN_SMEM>>>();

    // 3) output projection -> out (fp32)
    out_gemm_kernel<<<dim3(LL / 128, MROWS / 128), 256, GEMM_SMEM>>>(out);
}

// round 17
// speedup vs baseline: 2.0157x; 1.1221x over previous
#include <cuda_runtime.h>
#include <cuda_fp16.h>
#include <math.h>
#include <stdint.h>

// Problem constants
#define BB   2
#define SS   2048
#define LL   1024
#define HH   16
#define HKK  4
#define DD   64
#define MROWS (BB*SS)            // 4096
#define QKVN  ((HH + 2*HKK)*DD)  // 1536

// Scratch (allocation-free rule: __device__ globals). All fp16 storage.
__device__ __half g_xh  [MROWS * LL];     // x   -> fp16
__device__ __half g_w1h [QKVN * LL];      // w_qkv[0:1536] -> fp16
__device__ __half g_w2h [LL * LL];        // w_out -> fp16
__device__ __half g_qkv [MROWS * QKVN];   // qkv proj (Q cols pre-scaled), fp16
__device__ __half g_attn[MROWS * LL];     // attention output, fp16

// ---------------------------------------------------------------------------
// helpers
// ---------------------------------------------------------------------------
__device__ __forceinline__ unsigned packh2(float lo, float hi) {
    half2 h = __floats2half2_rn(lo, hi);
    return *(unsigned*)&h;
}

// D += A*B, m16n8k16 fp16 inputs, fp32 accumulate.
__device__ __forceinline__ void mma16(float* c, const unsigned* a, const unsigned* b) {
    asm volatile(
        "mma.sync.aligned.m16n8k16.row.col.f32.f16.f16.f32 "
        "{%0,%1,%2,%3}, {%4,%5,%6,%7}, {%8,%9}, {%0,%1,%2,%3};"
        : "+f"(c[0]), "+f"(c[1]), "+f"(c[2]), "+f"(c[3])
        : "r"(a[0]), "r"(a[1]), "r"(a[2]), "r"(a[3]),
          "r"(b[0]), "r"(b[1]));
}

__device__ __forceinline__ void ldsm4(unsigned& r0, unsigned& r1,
                                      unsigned& r2, unsigned& r3, uint32_t a) {
    asm volatile("ldmatrix.sync.aligned.m8n8.x4.shared.b16 {%0,%1,%2,%3}, [%4];"
                 : "=r"(r0), "=r"(r1), "=r"(r2), "=r"(r3) : "r"(a));
}

__device__ __forceinline__ void ldsm4t(unsigned& r0, unsigned& r1,
                                       unsigned& r2, unsigned& r3, uint32_t a) {
    asm volatile("ldmatrix.sync.aligned.m8n8.x4.trans.shared.b16 {%0,%1,%2,%3}, [%4];"
                 : "=r"(r0), "=r"(r1), "=r"(r2), "=r"(r3) : "r"(a));
}

__device__ __forceinline__ uint32_t smem_u32(const void* p) {
    uint32_t a;
    asm("{ .reg .u64 t; cvta.to.shared.u64 t, %1; cvt.u32.u64 %0, t; }"
        : "=r"(a) : "l"(p));
    return a;
}

__device__ __forceinline__ void cp16(uint32_t dst, const void* src) {
    asm volatile("cp.async.cg.shared.global [%0], [%1], 16;"
                 :: "r"(dst), "l"(src));
}
#define CP_COMMIT() asm volatile("cp.async.commit_group;" ::: "memory")
#define CP_WAIT0()  asm volatile("cp.async.wait_group 0;"  ::: "memory")
#define CP_WAIT1()  asm volatile("cp.async.wait_group 1;"  ::: "memory")
#define CP_WAIT2()  asm volatile("cp.async.wait_group 2;"  ::: "memory")

// ---------------------------------------------------------------------------
// One-time fp32 -> fp16 conversion: all three inputs in ONE launch.
// Segment sizes (in 1024-elem blocks): x 4096, w1 1536, w2 1024.
// ---------------------------------------------------------------------------
#define CVT_B0 (MROWS * LL / 1024)            // 4096
#define CVT_B1 (QKVN * LL / 1024)             // 1536
#define CVT_B2 (LL * LL / 1024)               // 1024

__global__ __launch_bounds__(256)
void cvt3_kernel(const float* __restrict__ x, const float* __restrict__ w1,
                 const float* __restrict__ w2)
{
    const float* src;
    __half* dst;
    int blk = blockIdx.x;
    if (blk < CVT_B0)                  { src = x;  dst = g_xh; }
    else if (blk < CVT_B0 + CVT_B1)    { src = w1; dst = g_w1h; blk -= CVT_B0; }
    else                               { src = w2; dst = g_w2h; blk -= CVT_B0 + CVT_B1; }
    const int i = (blk * 256 + threadIdx.x) * 4;
    float4 v = *(const float4*)(src + i);
    *(uint2*)(dst + i) = make_uint2(packh2(v.x, v.y), packh2(v.z, v.w));
}

// ---------------------------------------------------------------------------
// FP16 tensor-core GEMM (NT): C = A * B^T, fp32 accumulate.
// 128x128 CTA, BK=32 f16 per kt, 256 threads, warps 2(M)x4(N) -> 64x32 tiles.
// 4-stage cp.async pipeline. ALL fragment loads via ldmatrix.x4:
//   A: 1 x4 per m16 tile (4 per ks, was 16 LDS.32)
//   B: 1 x4 per n-tile PAIR x k16 (2 per ks, was 8 LDS.32)
// Rows: 16 data words + 4 pad = 20 (ldmatrix phase rows 20r mod 32 cover
// all banks -> conflict-free).
// ---------------------------------------------------------------------------
#define RW   20                               // row stride in u32 words
#define TILE_U (128 * RW)
#define STG  4
#define GEMM_SMEM (STG * 2 * TILE_U * 4)      // 81920 B -> 2 CTAs/SM

// OUTM: 0 = fp32 out, 1 = fp16 out with Q-prescale (bn < 1024 -> *0.125)
template <int OUTM>
__device__ __forceinline__
void gemm16_nt(const __half* __restrict__ A, const __half* __restrict__ B,
               void* __restrict__ C, int N, int K)
{
    extern __shared__ unsigned gsm[];

    const int bm   = blockIdx.y << 7;
    const int bn   = blockIdx.x << 7;
    const int tid  = threadIdx.x;
    const int lane = tid & 31;
    const int wid  = tid >> 5;
    const int wm   = wid >> 2;     // 0..1
    const int wn   = wid & 3;      // 0..3
    const int g    = lane >> 2;    // 0..7
    const int t4   = lane & 3;     // 0..3

    // ldmatrix per-lane address components
    const int a_row = (lane & 7) + 8 * ((lane >> 3) & 1);  // row within m16
    const int a_col = 4 * (lane >> 4);                     // word: k-half select
    const int b_row = (lane & 7) + 8 * (lane >> 4);        // row within n16 pair
    const int b_col = 4 * ((lane >> 3) & 1);               // word: k-half select

    // staging map
    const int r  = tid >> 1;
    const int q  = tid & 1;
    const __half* Ag = A + (size_t)(bm + r) * K + q * 16;
    const __half* Bg = B + (size_t)(bn + r) * K + q * 16;
    const uint32_t gb  = smem_u32(gsm);
    const uint32_t stgB = TILE_U * 4;
    const uint32_t asb = gb + (r * RW + q * 8) * 4;
    const uint32_t bsb = gb + STG * stgB + (r * RW + q * 8) * 4;

    float acc[4][4][4];
#pragma unroll
    for (int mt = 0; mt < 4; mt++)
#pragma unroll
        for (int nt = 0; nt < 4; nt++)
#pragma unroll
            for (int rr = 0; rr < 4; rr++) acc[mt][nt][rr] = 0.f;

    const int NT = K >> 5;   // 32 for K=1024

    // prologue: stage tiles 0..2
#pragma unroll
    for (int s = 0; s < STG - 1; s++) {
        const int ko = s << 5;
        const uint32_t off = s * stgB;
        cp16(asb + off,      Ag + ko);
        cp16(asb + off + 16, Ag + ko + 8);
        cp16(bsb + off,      Bg + ko);
        cp16(bsb + off + 16, Bg + ko + 8);
        CP_COMMIT();
    }

    for (int kt = 0; kt < NT; kt++) {
        CP_WAIT2();
        __syncthreads();

        if (kt + STG - 1 < NT) {
            const int ko = (kt + STG - 1) << 5;
            const uint32_t off = ((kt + STG - 1) & (STG - 1)) * stgB;
            cp16(asb + off,      Ag + ko);
            cp16(asb + off + 16, Ag + ko + 8);
            cp16(bsb + off,      Bg + ko);
            cp16(bsb + off + 16, Bg + ko + 8);
        }
        CP_COMMIT();

        const uint32_t as_b = gb + (kt & (STG - 1)) * stgB;
        const uint32_t bs_b = gb + STG * stgB + (kt & (STG - 1)) * stgB;

#pragma unroll
        for (int ks = 0; ks < 2; ks++) {
            const int kb = ks * 8;
            unsigned af[4][4], bf[4][2];
#pragma unroll
            for (int mt = 0; mt < 4; mt++) {
                const int row = wm * 64 + mt * 16 + a_row;
                ldsm4(af[mt][0], af[mt][1], af[mt][2], af[mt][3],
                      as_b + (row * RW + kb + a_col) * 4);
            }
#pragma unroll
            for (int p = 0; p < 2; p++) {
                const int nr = wn * 32 + p * 16 + b_row;
                ldsm4(bf[2*p][0], bf[2*p][1], bf[2*p+1][0], bf[2*p+1][1],
                      bs_b + (nr * RW + kb + b_col) * 4);
            }
#pragma unroll
            for (int mt = 0; mt < 4; mt++)
#pragma unroll
                for (int nt = 0; nt < 4; nt++)
                    mma16(acc[mt][nt], af[mt], bf[nt]);
        }
    }

    if (OUTM == 1) {
        const float s = (bn < 1024) ? 0.125f : 1.0f;
        __half* Ch = (__half*)C;
#pragma unroll
        for (int mt = 0; mt < 4; mt++) {
            const int row = bm + wm * 64 + mt * 16 + g;
#pragma unroll
            for (int nt = 0; nt < 4; nt++) {
                const int col = bn + wn * 32 + nt * 8 + 2 * t4;
                *(unsigned*)(Ch + (size_t)row * N + col) =
                    packh2(acc[mt][nt][0] * s, acc[mt][nt][1] * s);
                *(unsigned*)(Ch + (size_t)(row + 8) * N + col) =
                    packh2(acc[mt][nt][2] * s, acc[mt][nt][3] * s);
            }
        }
    } else {
        float* Cf = (float*)C;
#pragma unroll
        for (int mt = 0; mt < 4; mt++) {
            const int row = bm + wm * 64 + mt * 16 + g;
#pragma unroll
            for (int nt = 0; nt < 4; nt++) {
                const int col = bn + wn * 32 + nt * 8 + 2 * t4;
                *(float2*)(Cf + (size_t)row * N + col) =
                    make_float2(acc[mt][nt][0], acc[mt][nt][1]);
                *(float2*)(Cf + (size_t)(row + 8) * N + col) =
                    make_float2(acc[mt][nt][2], acc[mt][nt][3]);
            }
        }
    }
}

__global__ __launch_bounds__(256, 2)
void qkv_gemm_kernel()
{
    gemm16_nt<1>(g_xh, g_w1h, g_qkv, QKVN, LL);
}

__global__ __launch_bounds__(256, 2)
void out_gemm_kernel(float* __restrict__ out)
{
    gemm16_nt<0>(g_attn, g_w2h, out, LL, LL);
}

// ---------------------------------------------------------------------------
// Flash attention, causal, FP16 tensor cores (m16n8k16, fp32 accum).
// R16 structure with ALL QK fragment loads via ldmatrix.x4:
//   Q: 1 x4 per k16 (was 4 LDS), K: 4 x4 per k16 (was 16 LDS).
// Rows 72 f16 = 36 words: ldmatrix phase rows 4r mod 32 -> conflict-free.
// PV unchanged (C-frag == A-frag pack; V via ldmatrix.trans).
// ---------------------------------------------------------------------------
#define QTILE 128
#define ASTW  36
#define QW    (QTILE * ASTW)
#define KVW   (2 * 64 * ASTW)
#define ATTN_SMEM ((QW + 2 * KVW) * 4)        // 55296 B

__global__ __launch_bounds__(256, 2)
void attn_kernel()
{
    extern __shared__ unsigned sm[];

    const int qb   = gridDim.x - 1 - blockIdx.x;   // heavy first
    const int h    = blockIdx.y;
    const int b    = blockIdx.z;
    const int hk   = h >> 2;
    const int tid  = threadIdx.x;
    const int lane = tid & 31;
    const int w    = tid >> 5;
    const int g    = lane >> 2;
    const int t4   = lane & 3;
    const int R0   = 16 * w + g;
    const int gR0  = qb * QTILE + R0;

    const int a_row = (lane & 7) + 8 * ((lane >> 3) & 1);
    const int a_col = 4 * (lane >> 4);
    const int b_row = (lane & 7) + 8 * (lane >> 4);
    const int b_col = 4 * ((lane >> 3) & 1);

    const uint32_t smb = smem_u32(sm);

    auto stage_kv = [&](int buf, int kb) {
        const __half* kbase = g_qkv + (size_t)(b * SS + kb * 64) * QKVN
                              + HH * DD + hk * DD;
        const uint32_t ks_b = smb + (QW + buf * KVW) * 4;
        const uint32_t vs_b = ks_b + 64 * ASTW * 4;
#pragma unroll
        for (int i = 0; i < 2; i++) {
            const int e  = tid + i * 256;
            const int r  = e >> 3;
            const int c8 = (e & 7) * 8;
            const __half* p = kbase + (size_t)r * QKVN + c8;
            cp16(ks_b + (r * ASTW + c8 / 2) * 4, p);
            cp16(vs_b + (r * ASTW + c8 / 2) * 4, p + HKK * DD);
        }
    };

    // ---- group 0: Q tile + KV block 0 ----
    {
        const __half* qbase = g_qkv + (size_t)(b * SS + qb * QTILE) * QKVN + h * DD;
#pragma unroll
        for (int i = 0; i < 4; i++) {
            const int e  = tid + i * 256;
            const int r  = e >> 3;
            const int c8 = (e & 7) * 8;
            cp16(smb + (r * ASTW + c8 / 2) * 4, qbase + (size_t)r * QKVN + c8);
        }
        stage_kv(0, 0);
        CP_COMMIT();
    }

    float m0 = -1e30f, m1 = -1e30f, l0 = 0.f, l1 = 0.f;
    float oacc[8][4];
#pragma unroll
    for (int nt = 0; nt < 8; nt++)
#pragma unroll
        for (int r = 0; r < 4; r++) oacc[nt][r] = 0.f;

    const int kb_max = 2 * qb + 1;
    for (int kb = 0; kb <= kb_max; kb++) {
        if (kb < kb_max) {
            stage_kv((kb + 1) & 1, kb + 1);
            CP_COMMIT();
            CP_WAIT1();
        } else {
            CP_WAIT0();
        }
        __syncthreads();

        const uint32_t ks_b = smb + (QW + (kb & 1) * KVW) * 4;
        const uint32_t vs_b = ks_b + 64 * ASTW * 4;

        const bool active = (kb * 64 <= qb * QTILE + 16 * w + 15);
        if (active) {
            // ---- S = Q K^T : 4 k16 groups x 8 n-tiles, all ldmatrix ----
            float sacc[8][4];
#pragma unroll
            for (int nt = 0; nt < 8; nt++)
#pragma unroll
                for (int r = 0; r < 4; r++) sacc[nt][r] = 0.f;

            const int qrow = 16 * w + a_row;
#pragma unroll
            for (int kk = 0; kk < 4; kk++) {
                const int kw = kk * 8;
                unsigned af[4];
                ldsm4(af[0], af[1], af[2], af[3],
                      smb + (qrow * ASTW + kw + a_col) * 4);
                unsigned bf[8][2];
#pragma unroll
                for (int p = 0; p < 4; p++) {
                    const int nr = p * 16 + b_row;
                    ldsm4(bf[2*p][0], bf[2*p][1], bf[2*p+1][0], bf[2*p+1][1],
                          ks_b + (nr * ASTW + kw + b_col) * 4);
                }
#pragma unroll
                for (int nt = 0; nt < 8; nt++)
                    mma16(sacc[nt], af, bf[nt]);
            }

            // ---- causal mask ----
            if (kb * 64 + 63 > qb * QTILE + 16 * w) {
#pragma unroll
                for (int nt = 0; nt < 8; nt++) {
                    const int cc = kb * 64 + nt * 8 + 2 * t4;
                    if (cc     > gR0)     sacc[nt][0] = -1e30f;
                    if (cc + 1 > gR0)     sacc[nt][1] = -1e30f;
                    if (cc     > gR0 + 8) sacc[nt][2] = -1e30f;
                    if (cc + 1 > gR0 + 8) sacc[nt][3] = -1e30f;
                }
            }

            // ---- online softmax (fp32) ----
            float mx0 = -1e30f, mx1 = -1e30f;
#pragma unroll
            for (int nt = 0; nt < 8; nt++) {
                mx0 = fmaxf(mx0, fmaxf(sacc[nt][0], sacc[nt][1]));
                mx1 = fmaxf(mx1, fmaxf(sacc[nt][2], sacc[nt][3]));
            }
            mx0 = fmaxf(mx0, __shfl_xor_sync(0xffffffffu, mx0, 1));
            mx0 = fmaxf(mx0, __shfl_xor_sync(0xffffffffu, mx0, 2));
            mx1 = fmaxf(mx1, __shfl_xor_sync(0xffffffffu, mx1, 1));
            mx1 = fmaxf(mx1, __shfl_xor_sync(0xffffffffu, mx1, 2));

            const float mn0 = fmaxf(m0, mx0);
            const float mn1 = fmaxf(m1, mx1);
            float sum0 = 0.f, sum1 = 0.f;
#pragma unroll
            for (int nt = 0; nt < 8; nt++) {
                sacc[nt][0] = __expf(sacc[nt][0] - mn0);
                sacc[nt][1] = __expf(sacc[nt][1] - mn0);
                sacc[nt][2] = __expf(sacc[nt][2] - mn1);
                sacc[nt][3] = __expf(sacc[nt][3] - mn1);
                sum0 += sacc[nt][0] + sacc[nt][1];
                sum1 += sacc[nt][2] + sacc[nt][3];
            }
            sum0 += __shfl_xor_sync(0xffffffffu, sum0, 1);
            sum0 += __shfl_xor_sync(0xffffffffu, sum0, 2);
            sum1 += __shfl_xor_sync(0xffffffffu, sum1, 1);
            sum1 += __shfl_xor_sync(0xffffffffu, sum1, 2);

            const float a0 = __expf(m0 - mn0);
            const float a1 = __expf(m1 - mn1);
            l0 = l0 * a0 + sum0;  m0 = mn0;
            l1 = l1 * a1 + sum1;  m1 = mn1;
#pragma unroll
            for (int nt = 0; nt < 8; nt++) {
                oacc[nt][0] *= a0; oacc[nt][1] *= a0;
                oacc[nt][2] *= a1; oacc[nt][3] *= a1;
            }

            // ---- O += P*V : C-frag == k16 A-frag; V via ldmatrix.trans ----
#pragma unroll
            for (int kk = 0; kk < 4; kk++) {
                unsigned af[4];
                af[0] = packh2(sacc[2*kk    ][0], sacc[2*kk    ][1]);
                af[1] = packh2(sacc[2*kk    ][2], sacc[2*kk    ][3]);
                af[2] = packh2(sacc[2*kk + 1][0], sacc[2*kk + 1][1]);
                af[3] = packh2(sacc[2*kk + 1][2], sacc[2*kk + 1][3]);

                const int vrow = kk * 16 + (lane & 7) + 8 * ((lane >> 3) & 1);
                const int vcol0 = 8 * (lane >> 4);
#pragma unroll
                for (int j = 0; j < 4; j++) {
                    unsigned b0, b1, b2, b3;
                    const uint32_t addr =
                        vs_b + (vrow * ASTW * 2 + (j * 16 + vcol0)) * 2;
                    ldsm4t(b0, b1, b2, b3, addr);
                    unsigned bl[2] = {b0, b1};
                    mma16(oacc[2*j], af, bl);
                    unsigned bh[2] = {b2, b3};
                    mma16(oacc[2*j + 1], af, bh);
                }
            }
        }
        __syncthreads();
    }

    // ---- normalize + store fp16 (head-major [b,s,h,d]) ----
    const float inv0 = 1.f / l0;
    const float inv1 = 1.f / l1;
    __half* ob = g_attn + (size_t)(b * SS + qb * QTILE) * LL + h * DD;
#pragma unroll
    for (int nt = 0; nt < 8; nt++) {
        const int cc = nt * 8 + 2 * t4;
        *(unsigned*)(ob + (size_t)R0 * LL + cc) =
            packh2(oacc[nt][0] * inv0, oacc[nt][1] * inv0);
        *(unsigned*)(ob + (size_t)(R0 + 8) * LL + cc) =
            packh2(oacc[nt][2] * inv1, oacc[nt][3] * inv1);
    }
}

// ---------------------------------------------------------------------------
extern "C" void kernel_launch(void* const* d_in, const int* in_sizes, int n_in,
                              void* d_out, int out_size)
{
    const float* x = nullptr;
    const float* w_qkv = nullptr;
    const float* w_out = nullptr;
    for (int i = 0; i < n_in; i++) {
        if      (in_sizes[i] == 4194304) x     = (const float*)d_in[i];
        else if (in_sizes[i] == 3670016) w_qkv = (const float*)d_in[i];
        else if (in_sizes[i] == 1048576) w_out = (const float*)d_in[i];
    }
    float* out = (float*)d_out;

    static bool attr_set = false;
    if (!attr_set) {
        cudaFuncSetAttribute(attn_kernel,
                             cudaFuncAttributeMaxDynamicSharedMemorySize,
                             ATTN_SMEM);
        cudaFuncSetAttribute(qkv_gemm_kernel,
                             cudaFuncAttributeMaxDynamicSharedMemorySize,
                             GEMM_SMEM);
        cudaFuncSetAttribute(out_gemm_kernel,
                             cudaFuncAttributeMaxDynamicSharedMemorySize,
                             GEMM_SMEM);
        attr_set = true;
    }

    // 0) one-time fp32 -> fp16 conversion of all inputs (single launch)
    cvt3_kernel<<<CVT_B0 + CVT_B1 + CVT_B2, 256>>>(x, w_qkv, w_out);

    // 1) fused QKV projection -> g_qkv (fp16, Q pre-scaled)
    qkv_gemm_kernel<<<dim3(QKVN / 128, MROWS / 128), 256, GEMM_SMEM>>>();

    // 2) causal GQA flash attention -> g_attn (fp16)
    attn_kernel<<<dim3(SS / QTILE, HH, BB), 256, ATTN_SMEM>>>();

    // 3) output projection -> out (fp32)
    out_gemm_kernel<<<dim3(LL / 128, MROWS / 128), 256, GEMM_SMEM>>>(out);
}